// round 11
// baseline (speedup 1.0000x reference)
#include <cuda_runtime.h>
#include <math.h>

#define BATCH 8
#define NPTS  4096
#define KNN   16
#define CH    64
#define NTILE 16
#define SAMP  256            // NTILE * KNN samples per tile block
#define NBLK  2048           // BATCH * (NPTS / NTILE)

typedef unsigned long long ull;

// ---------------- device scratch (no allocations allowed) ----------------
__device__ float  g_rel[BATCH * NPTS * KNN * 3];        // 6.3 MB relative vectors
__device__ float  g_h1[(size_t)NBLK * CH * SAMP];       // 134 MB pre-BN block-1 activations
__device__ double g_mom[9];                             // rel moments
__device__ float  g_w1f[CH * 3];                        // BN0-folded w1
__device__ float  g_b1f[CH];
__device__ double g_s1[CH];                             // sum h1 per channel
__device__ double g_ss1[CH];                            // sum h1^2 per channel
__device__ float  g_a1[CH];                             // BN1 scale
__device__ float  g_c1[CH];                             // BN1 shift

// ---------------- f32x2 helpers (FFMA2: packed fp32, PTX-only) ----------------
__device__ __forceinline__ ull ffma2(ull a, ull b, ull c) {
    ull d;
    asm("fma.rn.f32x2 %0, %1, %2, %3;" : "=l"(d) : "l"(a), "l"(b), "l"(c));
    return d;
}
__device__ __forceinline__ ull pack2(float lo, float hi) {
    ull r;
    asm("mov.b64 %0, {%1, %2};" : "=l"(r) : "f"(lo), "f"(hi));
    return r;
}
__device__ __forceinline__ void unpack2(ull v, float& lo, float& hi) {
    asm("mov.b64 {%0, %1}, %2;" : "=f"(lo), "=f"(hi) : "l"(v));
}

#define LDS2(r0, r1, ptr) do { ulonglong2 _v = *(const ulonglong2*)(ptr); r0 = _v.x; r1 = _v.y; } while (0)

// ---------------- K0: zero the cross-launch accumulators ----------------
__global__ void k0_init() {
    int t = threadIdx.x;
    if (t < 9)  g_mom[t] = 0.0;
    if (t < CH) { g_s1[t] = 0.0; g_ss1[t] = 0.0; }
}

// ---------------- K1: KNN (ranks 2..17 by LARGEST distance) + rel + rel moments ----
__global__ __launch_bounds__(256) void k1_knn(const float* __restrict__ xyz) {
    extern __shared__ float4 pts[];      // 4096 x (x,y,z,|p|^2) = 64 KB
    __shared__ float sacc[9];
    const int t    = threadIdx.x;
    const int b    = blockIdx.x >> 4;
    const int tile = blockIdx.x & 15;
    const float* xb = xyz + (size_t)b * 3 * NPTS;
    for (int n = t; n < NPTS; n += 256) {
        float x = xb[n], y = xb[NPTS + n], z = xb[2 * NPTS + n];
        pts[n] = make_float4(x, y, z, fmaf(x, x, fmaf(y, y, z * z)));
    }
    if (t < 9) sacc[t] = 0.0f;
    __syncthreads();

    const int i = tile * 256 + t;
    const float4 q = pts[i];

    float bd[17]; int bi[17];
    #pragma unroll
    for (int u = 0; u < 17; ++u) { bd[u] = -1e30f; bi[u] = 0; }
    float cmin = -1e30f; int cpos = 0;

    #pragma unroll 4
    for (int j = 0; j < NPTS; ++j) {
        float4 p = pts[j];
        float dt = fmaf(q.x, p.x, fmaf(q.y, p.y, q.z * p.z));
        float d  = q.w + p.w - 2.0f * dt;
        if (d > cmin) {            // strict >: ties keep earlier (lower) index, like jax top_k
            bd[cpos] = d; bi[cpos] = j;
            cmin = bd[0]; cpos = 0;
            #pragma unroll
            for (int u = 1; u < 17; ++u)
                if (bd[u] < cmin) { cmin = bd[u]; cpos = u; }
        }
    }

    float mval = bd[0]; int mpos = 0;
    #pragma unroll
    for (int u = 1; u < 17; ++u)
        if (bd[u] > mval || (bd[u] == mval && bi[u] < bi[mpos])) { mval = bd[u]; mpos = u; }

    float sx=0,sy=0,sz=0,sxx=0,sxy=0,sxz=0,syy=0,syz=0,szz=0;
    float* outr = g_rel + (size_t)(b * NPTS + i) * (KNN * 3);
    int kk = 0;
    #pragma unroll
    for (int u = 0; u < 17; ++u) {
        if (u == mpos) continue;
        float4 p = pts[bi[u]];
        float rx = p.x - q.x, ry = p.y - q.y, rz = p.z - q.z;
        outr[kk*3+0] = rx; outr[kk*3+1] = ry; outr[kk*3+2] = rz;
        ++kk;
        sx += rx; sy += ry; sz += rz;
        sxx = fmaf(rx,rx,sxx); sxy = fmaf(rx,ry,sxy); sxz = fmaf(rx,rz,sxz);
        syy = fmaf(ry,ry,syy); syz = fmaf(ry,rz,syz); szz = fmaf(rz,rz,szz);
    }
    atomicAdd(&sacc[0],sx);  atomicAdd(&sacc[1],sy);  atomicAdd(&sacc[2],sz);
    atomicAdd(&sacc[3],sxx); atomicAdd(&sacc[4],sxy); atomicAdd(&sacc[5],sxz);
    atomicAdd(&sacc[6],syy); atomicAdd(&sacc[7],syz); atomicAdd(&sacc[8],szz);
    __syncthreads();
    if (t < 9) atomicAdd(&g_mom[t], (double)sacc[t]);
}

// ---------------- K2: fold block-0 BN into w1 (exact, from rel moments) ----------------
__global__ void k2_fold0(const float* __restrict__ w1, const float* __restrict__ b1,
                         const float* __restrict__ gamma, const float* __restrict__ beta) {
    int o = threadIdx.x;
    if (o >= CH) return;
    double inv = 1.0 / ((double)BATCH * NPTS * KNN);
    double m0=g_mom[0]*inv, m1=g_mom[1]*inv, m2=g_mom[2]*inv;
    double Mxx=g_mom[3]*inv, Mxy=g_mom[4]*inv, Mxz=g_mom[5]*inv;
    double Myy=g_mom[6]*inv, Myz=g_mom[7]*inv, Mzz=g_mom[8]*inv;
    double wx=w1[o*3+0], wy=w1[o*3+1], wz=w1[o*3+2], bb=b1[o];
    double wm = wx*m0 + wy*m1 + wz*m2;
    double mu = wm + bb;
    double e2 = wx*wx*Mxx + wy*wy*Myy + wz*wz*Mzz
              + 2.0*(wx*wy*Mxy + wx*wz*Mxz + wy*wz*Myz)
              + 2.0*bb*wm + bb*bb;
    double var = e2 - mu*mu;
    double a = (double)gamma[o] / sqrt(var + 1e-5);
    g_w1f[o*3+0]=(float)(a*wx); g_w1f[o*3+1]=(float)(a*wy); g_w1f[o*3+2]=(float)(a*wz);
    g_b1f[o]=(float)(a*(bb-mu) + (double)beta[o]);
}

// ---------------- K3: g1 = relu(BN0(w1 rel)); h1 = w2 g1 + b2 -> store + stats ----------------
__global__ __launch_bounds__(256) void k3_h1(const float* __restrict__ w2, const float* __restrict__ b2) {
    extern __shared__ float sm3[];
    float* g1s = sm3;                 // CH*SAMP (64 KB)
    float* w2d = sm3 + CH*SAMP;       // CH*CH duplicated pairs: [c][o]{w,w} (32 KB)
    __shared__ float w1fs[CH*3], b1fs[CH], sh1[CH], sq1[CH];
    __shared__ ull  b2p[CH];
    const int t  = threadIdx.x;
    const int b  = blockIdx.x >> 8;
    const int n0 = (blockIdx.x & 255) * NTILE;
    for (int idx = t; idx < CH*CH; idx += 256) {
        int o = idx >> 6, c = idx & 63;             // w2 row-major [o][c]
        float v = w2[idx];
        w2d[(c*CH + o)*2 + 0] = v;
        w2d[(c*CH + o)*2 + 1] = v;
    }
    if (t < CH*3) w1fs[t] = g_w1f[t];
    if (t < CH) { b1fs[t] = g_b1f[t]; float bv = b2[t]; b2p[t] = pack2(bv, bv);
                  sh1[t]=0.f; sq1[t]=0.f; }
    __syncthreads();

    {   // stage 1: g1 for this tile (sample s = n_local*16 + k)
        const int nl = t >> 4, k = t & 15;
        const float* r = g_rel + (size_t)((b*NPTS + n0 + nl)*KNN + k)*3;
        float rx=r[0], ry=r[1], rz=r[2];
        #pragma unroll 16
        for (int o = 0; o < CH; ++o) {
            float h = fmaf(w1fs[o*3], rx, fmaf(w1fs[o*3+1], ry, fmaf(w1fs[o*3+2], rz, b1fs[o])));
            g1s[o*SAMP + t] = fmaxf(h, 0.0f);
        }
    }
    __syncthreads();

    // stage 2: h1 — 2 sample-pairs x 16 channels per thread, packed f32x2,
    // g operand double-buffered, full unroll. Whole warp shares og -> w is broadcast LDS.
    const int og = t >> 6, st = t & 63;
    const int o0 = og*16, s0 = st*4;
    ull acc0[16], acc1[16];
    #pragma unroll
    for (int j=0;j<16;++j) { ull bv = b2p[o0+j]; acc0[j] = bv; acc1[j] = bv; }

    const float* gp = g1s + s0;
    const float* wp = w2d + o0*2;
    ull gA0, gA1, gB0, gB1;
    LDS2(gA0, gA1, gp);
    #pragma unroll
    for (int c = 0; c < CH; ++c) {
        if (c + 1 < CH) { LDS2(gB0, gB1, gp + (c+1)*SAMP); }
        const ulonglong2* wq = (const ulonglong2*)(wp + c*(CH*2));
        ulonglong2 w01 = wq[0], w23 = wq[1], w45 = wq[2], w67 = wq[3];
        ulonglong2 w89 = wq[4], wab = wq[5], wcd = wq[6], wef = wq[7];
        ull wv[16] = {w01.x,w01.y,w23.x,w23.y,w45.x,w45.y,w67.x,w67.y,
                      w89.x,w89.y,wab.x,wab.y,wcd.x,wcd.y,wef.x,wef.y};
        #pragma unroll
        for (int j=0;j<16;++j) {
            acc0[j] = ffma2(gA0, wv[j], acc0[j]);
            acc1[j] = ffma2(gA1, wv[j], acc1[j]);
        }
        gA0 = gB0; gA1 = gB1;
    }

    float* hb = g_h1 + (size_t)blockIdx.x * (CH*SAMP);
    #pragma unroll
    for (int j=0;j<16;++j) {
        float a0,a1,a2,a3;
        unpack2(acc0[j], a0, a1);
        unpack2(acc1[j], a2, a3);
        float s  = (a0 + a1) + (a2 + a3);
        float qq = fmaf(a0,a0, fmaf(a1,a1, fmaf(a2,a2, a3*a3)));
        atomicAdd(&sh1[o0+j], s);
        atomicAdd(&sq1[o0+j], qq);
        *(ulonglong2*)(hb + (o0+j)*SAMP + s0) = make_ulonglong2(acc0[j], acc1[j]);
    }
    __syncthreads();
    if (t < CH) { atomicAdd(&g_s1[t], (double)sh1[t]); atomicAdd(&g_ss1[t], (double)sq1[t]); }
}

// ---------------- K3b: finalize block-1 BN affine ----------------
__global__ void k3b_fold1(const float* __restrict__ gamma, const float* __restrict__ beta) {
    int o = threadIdx.x;
    if (o >= CH) return;
    double inv = 1.0 / ((double)BATCH * NPTS * KNN);
    double mu  = g_s1[o] * inv;
    double var = g_ss1[o] * inv - mu*mu;
    double a = (double)gamma[o] / sqrt(var + 1e-5);
    g_a1[o] = (float)a;
    g_c1[o] = (float)((double)beta[o] - a*mu);
}

// ---------------- K4: g2 = relu(BN1(h1)); h2 = w2 g2 + b2; max over k -> out ----------------
__global__ __launch_bounds__(256) void k4_out(const float* __restrict__ w2, const float* __restrict__ b2,
                                              float* __restrict__ out) {
    extern __shared__ float sm4[];
    float* g2s = sm4;                 // CH*SAMP (64 KB)
    float* w2d = sm4 + CH*SAMP;       // CH*CH duplicated pairs (32 KB)
    __shared__ float a1s[CH], c1s[CH];
    __shared__ ull  b2p[CH];
    const int t  = threadIdx.x;
    const int b  = blockIdx.x >> 8;
    const int n0 = (blockIdx.x & 255) * NTILE;
    for (int idx = t; idx < CH*CH; idx += 256) {
        int o = idx >> 6, c = idx & 63;
        float v = w2[idx];
        w2d[(c*CH + o)*2 + 0] = v;
        w2d[(c*CH + o)*2 + 1] = v;
    }
    if (t < CH) { a1s[t]=g_a1[t]; c1s[t]=g_c1[t]; float bv=b2[t]; b2p[t]=pack2(bv,bv); }
    __syncthreads();

    const float* hb = g_h1 + (size_t)blockIdx.x * (CH*SAMP);
    for (int idx = t*4; idx < CH*SAMP; idx += 256*4) {
        float4 v = *(const float4*)(hb + idx);
        int o = idx >> 8;                       // 4 elems stay inside one 256-wide row
        float a = a1s[o], c = c1s[o];
        v.x = fmaxf(fmaf(a,v.x,c),0.f);
        v.y = fmaxf(fmaf(a,v.y,c),0.f);
        v.z = fmaxf(fmaf(a,v.z,c),0.f);
        v.w = fmaxf(fmaf(a,v.w,c),0.f);
        *(float4*)(g2s + idx) = v;
    }
    __syncthreads();

    const int og = t >> 6, st = t & 63;
    const int o0 = og*16, s0 = st*4;
    ull acc0[16], acc1[16];
    #pragma unroll
    for (int j=0;j<16;++j) { ull bv = b2p[o0+j]; acc0[j] = bv; acc1[j] = bv; }

    const float* gp = g2s + s0;
    const float* wp = w2d + o0*2;
    ull gA0, gA1, gB0, gB1;
    LDS2(gA0, gA1, gp);
    #pragma unroll
    for (int c = 0; c < CH; ++c) {
        if (c + 1 < CH) { LDS2(gB0, gB1, gp + (c+1)*SAMP); }
        const ulonglong2* wq = (const ulonglong2*)(wp + c*(CH*2));
        ulonglong2 w01 = wq[0], w23 = wq[1], w45 = wq[2], w67 = wq[3];
        ulonglong2 w89 = wq[4], wab = wq[5], wcd = wq[6], wef = wq[7];
        ull wv[16] = {w01.x,w01.y,w23.x,w23.y,w45.x,w45.y,w67.x,w67.y,
                      w89.x,w89.y,wab.x,wab.y,wcd.x,wcd.y,wef.x,wef.y};
        #pragma unroll
        for (int j=0;j<16;++j) {
            acc0[j] = ffma2(gA0, wv[j], acc0[j]);
            acc1[j] = ffma2(gA1, wv[j], acc1[j]);
        }
        gA0 = gB0; gA1 = gB1;
    }

    // thread's 4 samples = 4 consecutive k of one point (s0 is 4-aligned within a 16-k group);
    // the 4 threads covering a point are adjacent lanes -> shfl reduction, no smem.
    const int n = n0 + (st >> 2);
    #pragma unroll
    for (int j=0;j<16;++j) {
        float a0,a1,a2,a3;
        unpack2(acc0[j], a0, a1);
        unpack2(acc1[j], a2, a3);
        float m = fmaxf(fmaxf(a0,a1), fmaxf(a2,a3));
        m = fmaxf(m, __shfl_xor_sync(0xFFFFFFFFu, m, 1));
        m = fmaxf(m, __shfl_xor_sync(0xFFFFFFFFu, m, 2));
        if ((st & 3) == 0)
            out[((size_t)(b*CH + o0 + j))*NPTS + n] = m;
    }
}

// ---------------- launch ----------------
extern "C" void kernel_launch(void* const* d_in, const int* in_sizes, int n_in,
                              void* d_out, int out_size) {
    const float* xyz   = (const float*)d_in[0];
    const float* w1    = (const float*)d_in[1];
    const float* b1    = (const float*)d_in[2];
    const float* w2    = (const float*)d_in[3];
    const float* b2    = (const float*)d_in[4];
    const float* gamma = (const float*)d_in[5];
    const float* beta  = (const float*)d_in[6];
    float* out = (float*)d_out;
    (void)in_sizes; (void)n_in; (void)out_size;

    cudaFuncSetAttribute(k1_knn, cudaFuncAttributeMaxDynamicSharedMemorySize, 65536);
    cudaFuncSetAttribute(k3_h1,  cudaFuncAttributeMaxDynamicSharedMemorySize, 98304);
    cudaFuncSetAttribute(k4_out, cudaFuncAttributeMaxDynamicSharedMemorySize, 98304);

    k0_init<<<1, 256>>>();
    k1_knn<<<128, 256, 65536>>>(xyz);
    k2_fold0<<<1, 64>>>(w1, b1, gamma, beta);
    k3_h1<<<NBLK, 256, 98304>>>(w2, b2);
    k3b_fold1<<<1, 64>>>(gamma, beta);
    k4_out<<<NBLK, 256, 98304>>>(w2, b2, out);
}

// round 12
// speedup vs baseline: 3.4096x; 3.4096x over previous
#include <cuda_runtime.h>
#include <math.h>

#define BATCH 8
#define NPTS  4096
#define KNN   16
#define CH    64
#define NTILE 16
#define SAMP  256            // NTILE * KNN samples per tile block
#define NBLK  2048           // BATCH * (NPTS / NTILE)

typedef unsigned long long ull;

// ---------------- device scratch (no allocations allowed) ----------------
__device__ float  g_rel[BATCH * NPTS * KNN * 3];        // 6.3 MB relative vectors
__device__ float  g_h1[(size_t)NBLK * CH * SAMP];       // 134 MB pre-BN block-1 activations
__device__ double g_mom[9];                             // rel moments
__device__ float  g_w1f[CH * 3];                        // BN0-folded w1
__device__ float  g_b1f[CH];
__device__ double g_s1[CH];                             // sum h1 per channel
__device__ double g_ss1[CH];                            // sum h1^2 per channel
__device__ float  g_a1[CH];                             // BN1 scale
__device__ float  g_c1[CH];                             // BN1 shift

// ---------------- f32x2 helpers (FFMA2: packed fp32, PTX-only) ----------------
__device__ __forceinline__ ull ffma2(ull a, ull b, ull c) {
    ull d;
    asm("fma.rn.f32x2 %0, %1, %2, %3;" : "=l"(d) : "l"(a), "l"(b), "l"(c));
    return d;
}
__device__ __forceinline__ ull pack2(float lo, float hi) {
    ull r;
    asm("mov.b64 %0, {%1, %2};" : "=l"(r) : "f"(lo), "f"(hi));
    return r;
}
__device__ __forceinline__ void unpack2(ull v, float& lo, float& hi) {
    asm("mov.b64 {%0, %1}, %2;" : "=f"(lo), "=f"(hi) : "l"(v));
}

#define LDS2(r0, r1, ptr) do { ulonglong2 _v = *(const ulonglong2*)(ptr); r0 = _v.x; r1 = _v.y; } while (0)

// ---------------- K0: zero the cross-launch accumulators ----------------
__global__ void k0_init() {
    int t = threadIdx.x;
    if (t < 9)  g_mom[t] = 0.0;
    if (t < CH) { g_s1[t] = 0.0; g_ss1[t] = 0.0; }
}

// ---------------- K1: KNN (ranks 2..17 by LARGEST distance) + rel + rel moments ----
__global__ __launch_bounds__(256) void k1_knn(const float* __restrict__ xyz) {
    extern __shared__ float4 pts[];      // 4096 x (x,y,z,|p|^2) = 64 KB
    __shared__ float sacc[9];
    const int t    = threadIdx.x;
    const int b    = blockIdx.x >> 4;
    const int tile = blockIdx.x & 15;
    const float* xb = xyz + (size_t)b * 3 * NPTS;
    for (int n = t; n < NPTS; n += 256) {
        float x = xb[n], y = xb[NPTS + n], z = xb[2 * NPTS + n];
        pts[n] = make_float4(x, y, z, fmaf(x, x, fmaf(y, y, z * z)));
    }
    if (t < 9) sacc[t] = 0.0f;
    __syncthreads();

    const int i = tile * 256 + t;
    const float4 q = pts[i];

    float bd[17]; int bi[17];
    #pragma unroll
    for (int u = 0; u < 17; ++u) { bd[u] = -1e30f; bi[u] = 0; }
    float cmin = -1e30f; int cpos = 0;

    #pragma unroll 4
    for (int j = 0; j < NPTS; ++j) {
        float4 p = pts[j];
        float dt = fmaf(q.x, p.x, fmaf(q.y, p.y, q.z * p.z));
        float d  = q.w + p.w - 2.0f * dt;
        if (d > cmin) {            // strict >: ties keep earlier (lower) index, like jax top_k
            bd[cpos] = d; bi[cpos] = j;
            cmin = bd[0]; cpos = 0;
            #pragma unroll
            for (int u = 1; u < 17; ++u)
                if (bd[u] < cmin) { cmin = bd[u]; cpos = u; }
        }
    }

    float mval = bd[0]; int mpos = 0;
    #pragma unroll
    for (int u = 1; u < 17; ++u)
        if (bd[u] > mval || (bd[u] == mval && bi[u] < bi[mpos])) { mval = bd[u]; mpos = u; }

    float sx=0,sy=0,sz=0,sxx=0,sxy=0,sxz=0,syy=0,syz=0,szz=0;
    float* outr = g_rel + (size_t)(b * NPTS + i) * (KNN * 3);
    int kk = 0;
    #pragma unroll
    for (int u = 0; u < 17; ++u) {
        if (u == mpos) continue;
        float4 p = pts[bi[u]];
        float rx = p.x - q.x, ry = p.y - q.y, rz = p.z - q.z;
        outr[kk*3+0] = rx; outr[kk*3+1] = ry; outr[kk*3+2] = rz;
        ++kk;
        sx += rx; sy += ry; sz += rz;
        sxx = fmaf(rx,rx,sxx); sxy = fmaf(rx,ry,sxy); sxz = fmaf(rx,rz,sxz);
        syy = fmaf(ry,ry,syy); syz = fmaf(ry,rz,syz); szz = fmaf(rz,rz,szz);
    }
    atomicAdd(&sacc[0],sx);  atomicAdd(&sacc[1],sy);  atomicAdd(&sacc[2],sz);
    atomicAdd(&sacc[3],sxx); atomicAdd(&sacc[4],sxy); atomicAdd(&sacc[5],sxz);
    atomicAdd(&sacc[6],syy); atomicAdd(&sacc[7],syz); atomicAdd(&sacc[8],szz);
    __syncthreads();
    if (t < 9) atomicAdd(&g_mom[t], (double)sacc[t]);
}

// ---------------- K2: fold block-0 BN into w1 (exact, from rel moments) ----------------
__global__ void k2_fold0(const float* __restrict__ w1, const float* __restrict__ b1,
                         const float* __restrict__ gamma, const float* __restrict__ beta) {
    int o = threadIdx.x;
    if (o >= CH) return;
    double inv = 1.0 / ((double)BATCH * NPTS * KNN);
    double m0=g_mom[0]*inv, m1=g_mom[1]*inv, m2=g_mom[2]*inv;
    double Mxx=g_mom[3]*inv, Mxy=g_mom[4]*inv, Mxz=g_mom[5]*inv;
    double Myy=g_mom[6]*inv, Myz=g_mom[7]*inv, Mzz=g_mom[8]*inv;
    double wx=w1[o*3+0], wy=w1[o*3+1], wz=w1[o*3+2], bb=b1[o];
    double wm = wx*m0 + wy*m1 + wz*m2;
    double mu = wm + bb;
    double e2 = wx*wx*Mxx + wy*wy*Myy + wz*wz*Mzz
              + 2.0*(wx*wy*Mxy + wx*wz*Mxz + wy*wz*Myz)
              + 2.0*bb*wm + bb*bb;
    double var = e2 - mu*mu;
    double a = (double)gamma[o] / sqrt(var + 1e-5);
    g_w1f[o*3+0]=(float)(a*wx); g_w1f[o*3+1]=(float)(a*wy); g_w1f[o*3+2]=(float)(a*wz);
    g_b1f[o]=(float)(a*(bb-mu) + (double)beta[o]);
}

// ---------------- K3: g1 = relu(BN0(w1 rel)); h1 = w2 g1 + b2 -> store + stats ----------------
__global__ __launch_bounds__(256, 2) void k3_h1(const float* __restrict__ w2, const float* __restrict__ b2) {
    extern __shared__ float sm3[];
    float* g1s = sm3;                 // CH*SAMP (64 KB)
    float* w2d = sm3 + CH*SAMP;       // CH*CH duplicated pairs: [c][o]{w,w} (32 KB)
    __shared__ float w1fs[CH*3], b1fs[CH], sh1[CH], sq1[CH];
    __shared__ ull  b2p[CH];
    const int t  = threadIdx.x;
    const int b  = blockIdx.x >> 8;
    const int n0 = (blockIdx.x & 255) * NTILE;
    for (int idx = t; idx < CH*CH; idx += 256) {
        int o = idx >> 6, c = idx & 63;             // w2 row-major [o][c]
        float v = w2[idx];
        w2d[(c*CH + o)*2 + 0] = v;
        w2d[(c*CH + o)*2 + 1] = v;
    }
    if (t < CH*3) w1fs[t] = g_w1f[t];
    if (t < CH) { b1fs[t] = g_b1f[t]; float bv = b2[t]; b2p[t] = pack2(bv, bv);
                  sh1[t]=0.f; sq1[t]=0.f; }
    __syncthreads();

    {   // stage 1: g1 for this tile (sample s = n_local*16 + k)
        const int nl = t >> 4, k = t & 15;
        const float* r = g_rel + (size_t)((b*NPTS + n0 + nl)*KNN + k)*3;
        float rx=r[0], ry=r[1], rz=r[2];
        #pragma unroll 16
        for (int o = 0; o < CH; ++o) {
            float h = fmaf(w1fs[o*3], rx, fmaf(w1fs[o*3+1], ry, fmaf(w1fs[o*3+2], rz, b1fs[o])));
            g1s[o*SAMP + t] = fmaxf(h, 0.0f);
        }
    }
    __syncthreads();

    // stage 2: warp -> 8 channels (o0 = warp*8, w broadcast); lane -> samples
    // [l*4, l*4+4) and [128+l*4, 128+l*4+4) (both coalesced 16B LDS.128).
    // acc: 8 ch x 4 f32x2 pairs = 32 ull. g double-buffered.
    const int warp = t >> 5, lane = t & 31;
    const int o0 = warp * 8, l4 = lane * 4;
    ull acc[4][8];
    #pragma unroll
    for (int j=0;j<8;++j) {
        ull bv = b2p[o0+j];
        #pragma unroll
        for (int i=0;i<4;++i) acc[i][j] = bv;
    }

    const float* gp = g1s + l4;
    const float* wp = w2d + o0*2;
    ull gA0,gA1,gA2,gA3, gB0,gB1,gB2,gB3;
    LDS2(gA0, gA1, gp);
    LDS2(gA2, gA3, gp + 128);
    #pragma unroll
    for (int c = 0; c < CH; ++c) {
        if (c + 1 < CH) {
            LDS2(gB0, gB1, gp + (c+1)*SAMP);
            LDS2(gB2, gB3, gp + (c+1)*SAMP + 128);
        }
        const ulonglong2* wq = (const ulonglong2*)(wp + c*(CH*2));
        ulonglong2 w01 = wq[0], w23 = wq[1], w45 = wq[2], w67 = wq[3];
        ull wv[8] = {w01.x,w01.y,w23.x,w23.y,w45.x,w45.y,w67.x,w67.y};
        ull gv[4] = {gA0, gA1, gA2, gA3};
        #pragma unroll
        for (int i=0;i<4;++i)
            #pragma unroll
            for (int j=0;j<8;++j)
                acc[i][j] = ffma2(gv[i], wv[j], acc[i][j]);
        gA0 = gB0; gA1 = gB1; gA2 = gB2; gA3 = gB3;
    }

    float* hb = g_h1 + (size_t)blockIdx.x * (CH*SAMP);
    #pragma unroll
    for (int j=0;j<8;++j) {
        float a0,a1,a2,a3,a4,a5,a6,a7;
        unpack2(acc[0][j], a0, a1);
        unpack2(acc[1][j], a2, a3);
        unpack2(acc[2][j], a4, a5);
        unpack2(acc[3][j], a6, a7);
        float s  = ((a0+a1)+(a2+a3)) + ((a4+a5)+(a6+a7));
        float qq = fmaf(a0,a0, fmaf(a1,a1, fmaf(a2,a2, a3*a3)));
        qq = fmaf(a4,a4, fmaf(a5,a5, fmaf(a6,a6, fmaf(a7,a7, qq))));
        atomicAdd(&sh1[o0+j], s);
        atomicAdd(&sq1[o0+j], qq);
        *(ulonglong2*)(hb + (o0+j)*SAMP + l4)       = make_ulonglong2(acc[0][j], acc[1][j]);
        *(ulonglong2*)(hb + (o0+j)*SAMP + 128 + l4) = make_ulonglong2(acc[2][j], acc[3][j]);
    }
    __syncthreads();
    if (t < CH) { atomicAdd(&g_s1[t], (double)sh1[t]); atomicAdd(&g_ss1[t], (double)sq1[t]); }
}

// ---------------- K3b: finalize block-1 BN affine ----------------
__global__ void k3b_fold1(const float* __restrict__ gamma, const float* __restrict__ beta) {
    int o = threadIdx.x;
    if (o >= CH) return;
    double inv = 1.0 / ((double)BATCH * NPTS * KNN);
    double mu  = g_s1[o] * inv;
    double var = g_ss1[o] * inv - mu*mu;
    double a = (double)gamma[o] / sqrt(var + 1e-5);
    g_a1[o] = (float)a;
    g_c1[o] = (float)((double)beta[o] - a*mu);
}

// ---------------- K4: g2 = relu(BN1(h1)); h2 = w2 g2 + b2; max over k -> out ----------------
__global__ __launch_bounds__(256, 2) void k4_out(const float* __restrict__ w2, const float* __restrict__ b2,
                                                  float* __restrict__ out) {
    extern __shared__ float sm4[];
    float* g2s = sm4;                 // CH*SAMP (64 KB)
    float* w2d = sm4 + CH*SAMP;       // CH*CH duplicated pairs (32 KB)
    __shared__ float a1s[CH], c1s[CH];
    __shared__ ull  b2p[CH];
    const int t  = threadIdx.x;
    const int b  = blockIdx.x >> 8;
    const int n0 = (blockIdx.x & 255) * NTILE;
    for (int idx = t; idx < CH*CH; idx += 256) {
        int o = idx >> 6, c = idx & 63;
        float v = w2[idx];
        w2d[(c*CH + o)*2 + 0] = v;
        w2d[(c*CH + o)*2 + 1] = v;
    }
    if (t < CH) { a1s[t]=g_a1[t]; c1s[t]=g_c1[t]; float bv=b2[t]; b2p[t]=pack2(bv,bv); }
    __syncthreads();

    const float* hb = g_h1 + (size_t)blockIdx.x * (CH*SAMP);
    for (int idx = t*4; idx < CH*SAMP; idx += 256*4) {
        float4 v = *(const float4*)(hb + idx);
        int o = idx >> 8;                       // 4 elems stay inside one 256-wide row
        float a = a1s[o], c = c1s[o];
        v.x = fmaxf(fmaf(a,v.x,c),0.f);
        v.y = fmaxf(fmaf(a,v.y,c),0.f);
        v.z = fmaxf(fmaf(a,v.z,c),0.f);
        v.w = fmaxf(fmaf(a,v.w,c),0.f);
        *(float4*)(g2s + idx) = v;
    }
    __syncthreads();

    const int warp = t >> 5, lane = t & 31;
    const int o0 = warp * 8, l4 = lane * 4;
    ull acc[4][8];
    #pragma unroll
    for (int j=0;j<8;++j) {
        ull bv = b2p[o0+j];
        #pragma unroll
        for (int i=0;i<4;++i) acc[i][j] = bv;
    }

    const float* gp = g2s + l4;
    const float* wp = w2d + o0*2;
    ull gA0,gA1,gA2,gA3, gB0,gB1,gB2,gB3;
    LDS2(gA0, gA1, gp);
    LDS2(gA2, gA3, gp + 128);
    #pragma unroll
    for (int c = 0; c < CH; ++c) {
        if (c + 1 < CH) {
            LDS2(gB0, gB1, gp + (c+1)*SAMP);
            LDS2(gB2, gB3, gp + (c+1)*SAMP + 128);
        }
        const ulonglong2* wq = (const ulonglong2*)(wp + c*(CH*2));
        ulonglong2 w01 = wq[0], w23 = wq[1], w45 = wq[2], w67 = wq[3];
        ull wv[8] = {w01.x,w01.y,w23.x,w23.y,w45.x,w45.y,w67.x,w67.y};
        ull gv[4] = {gA0, gA1, gA2, gA3};
        #pragma unroll
        for (int i=0;i<4;++i)
            #pragma unroll
            for (int j=0;j<8;++j)
                acc[i][j] = ffma2(gv[i], wv[j], acc[i][j]);
        gA0 = gB0; gA1 = gB1; gA2 = gB2; gA3 = gB3;
    }

    // Lane's samples: 4 k-values of point p = lane>>2 (first half) and of point
    // 8+p (second half), k-quarter = lane&3. Lanes 4p..4p+3 are adjacent ->
    // shfl_xor(1,2) reduces the max over all 16 k of each point. No smem.
    const int pq = lane & 3;
    const int n  = n0 + (lane >> 2);
    #pragma unroll
    for (int j=0;j<8;++j) {
        float a0,a1,a2,a3,a4,a5,a6,a7;
        unpack2(acc[0][j], a0, a1);
        unpack2(acc[1][j], a2, a3);
        unpack2(acc[2][j], a4, a5);
        unpack2(acc[3][j], a6, a7);
        float m0 = fmaxf(fmaxf(a0,a1), fmaxf(a2,a3));   // point n, this k-quarter
        float m1 = fmaxf(fmaxf(a4,a5), fmaxf(a6,a7));   // point n+8
        m0 = fmaxf(m0, __shfl_xor_sync(0xFFFFFFFFu, m0, 1));
        m0 = fmaxf(m0, __shfl_xor_sync(0xFFFFFFFFu, m0, 2));
        m1 = fmaxf(m1, __shfl_xor_sync(0xFFFFFFFFu, m1, 1));
        m1 = fmaxf(m1, __shfl_xor_sync(0xFFFFFFFFu, m1, 2));
        if (pq == 0) {
            size_t base = ((size_t)(b*CH + o0 + j))*NPTS;
            out[base + n]     = m0;
            out[base + n + 8] = m1;
        }
    }
}

// ---------------- launch ----------------
extern "C" void kernel_launch(void* const* d_in, const int* in_sizes, int n_in,
                              void* d_out, int out_size) {
    const float* xyz   = (const float*)d_in[0];
    const float* w1    = (const float*)d_in[1];
    const float* b1    = (const float*)d_in[2];
    const float* w2    = (const float*)d_in[3];
    const float* b2    = (const float*)d_in[4];
    const float* gamma = (const float*)d_in[5];
    const float* beta  = (const float*)d_in[6];
    float* out = (float*)d_out;
    (void)in_sizes; (void)n_in; (void)out_size;

    cudaFuncSetAttribute(k1_knn, cudaFuncAttributeMaxDynamicSharedMemorySize, 65536);
    cudaFuncSetAttribute(k3_h1,  cudaFuncAttributeMaxDynamicSharedMemorySize, 98304);
    cudaFuncSetAttribute(k4_out, cudaFuncAttributeMaxDynamicSharedMemorySize, 98304);

    k0_init<<<1, 256>>>();
    k1_knn<<<128, 256, 65536>>>(xyz);
    k2_fold0<<<1, 64>>>(w1, b1, gamma, beta);
    k3_h1<<<NBLK, 256, 98304>>>(w2, b2);
    k3b_fold1<<<1, 64>>>(gamma, beta);
    k4_out<<<NBLK, 256, 98304>>>(w2, b2, out);
}

// round 13
// speedup vs baseline: 4.3823x; 1.2853x over previous
#include <cuda_runtime.h>
#include <math.h>
#include <stdint.h>

#define BATCH 8
#define NPTS  4096
#define KNN   16
#define CH    64
#define NTILE 16
#define SAMP  256            // NTILE * KNN samples per tile block
#define NBLK  2048           // BATCH * (NPTS / NTILE)
#define GPAD  68             // padded row length (floats) for [s][c] smem tiles

// ---------------- device scratch (no allocations allowed) ----------------
__device__ float  g_rel[BATCH * NPTS * KNN * 3];        // 6.3 MB relative vectors
__device__ float  g_h1[(size_t)NBLK * SAMP * CH];       // 134 MB h1, layout [block][s][o]
__device__ double g_mom[9];                             // rel moments
__device__ float  g_w1f[CH * 3];                        // BN0-folded w1
__device__ float  g_b1f[CH];
__device__ double g_s1[CH];                             // sum h1 per channel
__device__ double g_ss1[CH];                            // sum h1^2 per channel
__device__ float  g_a1[CH];                             // BN1 scale
__device__ float  g_c1[CH];                             // BN1 shift

// ---------------- tf32 helpers ----------------
__device__ __forceinline__ uint32_t f2tf32(float x) {
    uint32_t r;
    asm("cvt.rna.tf32.f32 %0, %1;" : "=r"(r) : "f"(x));
    return r;
}
__device__ __forceinline__ void tf32_split(float x, uint32_t& hi, uint32_t& lo) {
    hi = f2tf32(x);
    float rem = x - __uint_as_float(hi);
    lo = f2tf32(rem);
}
__device__ __forceinline__ void mma_tf32(float& c0, float& c1, float& c2, float& c3,
                                         uint32_t a0, uint32_t a1, uint32_t a2, uint32_t a3,
                                         uint32_t b0, uint32_t b1) {
    asm("mma.sync.aligned.m16n8k8.row.col.f32.tf32.tf32.f32 "
        "{%0,%1,%2,%3}, {%4,%5,%6,%7}, {%8,%9}, {%0,%1,%2,%3};"
        : "+f"(c0), "+f"(c1), "+f"(c2), "+f"(c3)
        : "r"(a0), "r"(a1), "r"(a2), "r"(a3), "r"(b0), "r"(b1));
}

// ---------------- K0: zero the cross-launch accumulators ----------------
__global__ void k0_init() {
    int t = threadIdx.x;
    if (t < 9)  g_mom[t] = 0.0;
    if (t < CH) { g_s1[t] = 0.0; g_ss1[t] = 0.0; }
}

// ---------------- K1: KNN (ranks 2..17 by LARGEST distance) + rel + rel moments ----
__global__ __launch_bounds__(256) void k1_knn(const float* __restrict__ xyz) {
    extern __shared__ float4 pts[];      // 4096 x (x,y,z,|p|^2) = 64 KB
    __shared__ float sacc[9];
    const int t    = threadIdx.x;
    const int b    = blockIdx.x >> 4;
    const int tile = blockIdx.x & 15;
    const float* xb = xyz + (size_t)b * 3 * NPTS;
    for (int n = t; n < NPTS; n += 256) {
        float x = xb[n], y = xb[NPTS + n], z = xb[2 * NPTS + n];
        pts[n] = make_float4(x, y, z, fmaf(x, x, fmaf(y, y, z * z)));
    }
    if (t < 9) sacc[t] = 0.0f;
    __syncthreads();

    const int i = tile * 256 + t;
    const float4 q = pts[i];

    float bd[17]; int bi[17];
    #pragma unroll
    for (int u = 0; u < 17; ++u) { bd[u] = -1e30f; bi[u] = 0; }
    float cmin = -1e30f; int cpos = 0;

    #pragma unroll 4
    for (int j = 0; j < NPTS; ++j) {
        float4 p = pts[j];
        float dt = fmaf(q.x, p.x, fmaf(q.y, p.y, q.z * p.z));
        float d  = q.w + p.w - 2.0f * dt;
        if (d > cmin) {            // strict >: ties keep earlier (lower) index, like jax top_k
            bd[cpos] = d; bi[cpos] = j;
            cmin = bd[0]; cpos = 0;
            #pragma unroll
            for (int u = 1; u < 17; ++u)
                if (bd[u] < cmin) { cmin = bd[u]; cpos = u; }
        }
    }

    float mval = bd[0]; int mpos = 0;
    #pragma unroll
    for (int u = 1; u < 17; ++u)
        if (bd[u] > mval || (bd[u] == mval && bi[u] < bi[mpos])) { mval = bd[u]; mpos = u; }

    float sx=0,sy=0,sz=0,sxx=0,sxy=0,sxz=0,syy=0,syz=0,szz=0;
    float* outr = g_rel + (size_t)(b * NPTS + i) * (KNN * 3);
    int kk = 0;
    #pragma unroll
    for (int u = 0; u < 17; ++u) {
        if (u == mpos) continue;
        float4 p = pts[bi[u]];
        float rx = p.x - q.x, ry = p.y - q.y, rz = p.z - q.z;
        outr[kk*3+0] = rx; outr[kk*3+1] = ry; outr[kk*3+2] = rz;
        ++kk;
        sx += rx; sy += ry; sz += rz;
        sxx = fmaf(rx,rx,sxx); sxy = fmaf(rx,ry,sxy); sxz = fmaf(rx,rz,sxz);
        syy = fmaf(ry,ry,syy); syz = fmaf(ry,rz,syz); szz = fmaf(rz,rz,szz);
    }
    atomicAdd(&sacc[0],sx);  atomicAdd(&sacc[1],sy);  atomicAdd(&sacc[2],sz);
    atomicAdd(&sacc[3],sxx); atomicAdd(&sacc[4],sxy); atomicAdd(&sacc[5],sxz);
    atomicAdd(&sacc[6],syy); atomicAdd(&sacc[7],syz); atomicAdd(&sacc[8],szz);
    __syncthreads();
    if (t < 9) atomicAdd(&g_mom[t], (double)sacc[t]);
}

// ---------------- K2: fold block-0 BN into w1 (exact, from rel moments) ----------------
__global__ void k2_fold0(const float* __restrict__ w1, const float* __restrict__ b1,
                         const float* __restrict__ gamma, const float* __restrict__ beta) {
    int o = threadIdx.x;
    if (o >= CH) return;
    double inv = 1.0 / ((double)BATCH * NPTS * KNN);
    double m0=g_mom[0]*inv, m1=g_mom[1]*inv, m2=g_mom[2]*inv;
    double Mxx=g_mom[3]*inv, Mxy=g_mom[4]*inv, Mxz=g_mom[5]*inv;
    double Myy=g_mom[6]*inv, Myz=g_mom[7]*inv, Mzz=g_mom[8]*inv;
    double wx=w1[o*3+0], wy=w1[o*3+1], wz=w1[o*3+2], bb=b1[o];
    double wm = wx*m0 + wy*m1 + wz*m2;
    double mu = wm + bb;
    double e2 = wx*wx*Mxx + wy*wy*Myy + wz*wz*Mzz
              + 2.0*(wx*wy*Mxy + wx*wz*Mxz + wy*wz*Myz)
              + 2.0*bb*wm + bb*bb;
    double var = e2 - mu*mu;
    double a = (double)gamma[o] / sqrt(var + 1e-5);
    g_w1f[o*3+0]=(float)(a*wx); g_w1f[o*3+1]=(float)(a*wy); g_w1f[o*3+2]=(float)(a*wz);
    g_b1f[o]=(float)(a*(bb-mu) + (double)beta[o]);
}

// ---------------- K3: g1 = relu(BN0(w1 rel)); h1 = w2 g1 + b2 (tf32 3-pass MMA) ----
__global__ __launch_bounds__(256, 2) void k3_h1(const float* __restrict__ w2, const float* __restrict__ b2) {
    extern __shared__ float sm3[];
    float* g1s = sm3;                  // [256][GPAD]  (69632 B)
    float* w2s = sm3 + SAMP*GPAD;      // [64][64] plain (16384 B)
    __shared__ float w1fs[CH*3], b1fs[CH], b2s[CH], sh1[CH], sq1[CH];
    const int t  = threadIdx.x;
    const int b  = blockIdx.x >> 8;
    const int n0blk = (blockIdx.x & 255) * NTILE;

    for (int idx = t; idx < CH*CH; idx += 256) w2s[idx] = w2[idx];
    if (t < CH*3) w1fs[t] = g_w1f[t];
    if (t < CH) { b1fs[t] = g_b1f[t]; b2s[t] = b2[t]; sh1[t]=0.f; sq1[t]=0.f; }
    __syncthreads();

    {   // stage 1: g1 for this tile; sample s = t = nl*16 + k; write [s][c] rows
        const int nl = t >> 4, k = t & 15;
        const float* r = g_rel + (size_t)((b*NPTS + n0blk + nl)*KNN + k)*3;
        float rx=r[0], ry=r[1], rz=r[2];
        float* row = g1s + t*GPAD;
        #pragma unroll
        for (int o = 0; o < CH; o += 4) {
            float4 v;
            v.x = fmaxf(fmaf(w1fs[(o+0)*3], rx, fmaf(w1fs[(o+0)*3+1], ry, fmaf(w1fs[(o+0)*3+2], rz, b1fs[o+0]))), 0.f);
            v.y = fmaxf(fmaf(w1fs[(o+1)*3], rx, fmaf(w1fs[(o+1)*3+1], ry, fmaf(w1fs[(o+1)*3+2], rz, b1fs[o+1]))), 0.f);
            v.z = fmaxf(fmaf(w1fs[(o+2)*3], rx, fmaf(w1fs[(o+2)*3+1], ry, fmaf(w1fs[(o+2)*3+2], rz, b1fs[o+2]))), 0.f);
            v.w = fmaxf(fmaf(w1fs[(o+3)*3], rx, fmaf(w1fs[(o+3)*3+1], ry, fmaf(w1fs[(o+3)*3+2], rz, b1fs[o+3]))), 0.f);
            *(float4*)(row + o) = v;
        }
    }
    __syncthreads();

    // mma stage: warp -> 16 out rows (m0) x 128 samples (shalf)
    const int warp = t >> 5, lane = t & 31, lr = lane >> 2, lc = lane & 3;
    const int m0 = (warp & 3) * 16, shalf = warp >> 2;

    // Load W frags (hi+lo) once: A row-major 16x8 per k-step
    uint32_t ahi[8][4], alo[8][4];
    #pragma unroll
    for (int kk = 0; kk < 8; ++kk) {
        int c0i = kk*8 + lc;
        tf32_split(w2s[(m0+lr  )*CH + c0i    ], ahi[kk][0], alo[kk][0]);
        tf32_split(w2s[(m0+lr+8)*CH + c0i    ], ahi[kk][1], alo[kk][1]);
        tf32_split(w2s[(m0+lr  )*CH + c0i + 4], ahi[kk][2], alo[kk][2]);
        tf32_split(w2s[(m0+lr+8)*CH + c0i + 4], ahi[kk][3], alo[kk][3]);
    }

    float bias0 = b2s[m0+lr], bias1 = b2s[m0+8+lr];
    float sum0=0.f, ssq0=0.f, sum1=0.f, ssq1=0.f;
    float* hb = g_h1 + (size_t)blockIdx.x * (SAMP*CH);

    for (int nt = 0; nt < 16; ++nt) {
        const int n0 = shalf*128 + nt*8;
        float h0=bias0,h1=bias0,h2=bias1,h3=bias1;   // Ahi*Bhi accumulator (+bias)
        float m0a=0,m1a=0,m2a=0,m3a=0;               // Ahi*Blo
        float l0=0,l1=0,l2=0,l3=0;                   // Alo*Bhi
        const float* grow = g1s + (n0+lr)*GPAD;
        #pragma unroll
        for (int kk = 0; kk < 8; ++kk) {
            float b0f = grow[kk*8 + lc];
            float b1f = grow[kk*8 + lc + 4];
            uint32_t bh0, bl0, bh1, bl1;
            tf32_split(b0f, bh0, bl0);
            tf32_split(b1f, bh1, bl1);
            mma_tf32(h0,h1,h2,h3, ahi[kk][0],ahi[kk][1],ahi[kk][2],ahi[kk][3], bh0,bh1);
            mma_tf32(m0a,m1a,m2a,m3a, ahi[kk][0],ahi[kk][1],ahi[kk][2],ahi[kk][3], bl0,bl1);
            mma_tf32(l0,l1,l2,l3, alo[kk][0],alo[kk][1],alo[kk][2],alo[kk][3], bh0,bh1);
        }
        float c0 = h0 + (m0a + l0);
        float c1 = h1 + (m1a + l1);
        float c2 = h2 + (m2a + l2);
        float c3 = h3 + (m3a + l3);
        // acc layout: c0:(o=m0+lr, s=n0+2lc) c1:s+1  c2:(o=m0+8+lr, s=n0+2lc) c3:s+1
        const int s0 = n0 + 2*lc;
        hb[(s0  )*CH + m0+lr  ] = c0;
        hb[(s0+1)*CH + m0+lr  ] = c1;
        hb[(s0  )*CH + m0+8+lr] = c2;
        hb[(s0+1)*CH + m0+8+lr] = c3;
        sum0 += c0 + c1;  ssq0 = fmaf(c0,c0, fmaf(c1,c1, ssq0));
        sum1 += c2 + c3;  ssq1 = fmaf(c2,c2, fmaf(c3,c3, ssq1));
    }
    // reduce stats across the 4 lanes sharing channels (same lr)
    sum0 += __shfl_xor_sync(0xFFFFFFFFu, sum0, 1); sum0 += __shfl_xor_sync(0xFFFFFFFFu, sum0, 2);
    ssq0 += __shfl_xor_sync(0xFFFFFFFFu, ssq0, 1); ssq0 += __shfl_xor_sync(0xFFFFFFFFu, ssq0, 2);
    sum1 += __shfl_xor_sync(0xFFFFFFFFu, sum1, 1); sum1 += __shfl_xor_sync(0xFFFFFFFFu, sum1, 2);
    ssq1 += __shfl_xor_sync(0xFFFFFFFFu, ssq1, 1); ssq1 += __shfl_xor_sync(0xFFFFFFFFu, ssq1, 2);
    if (lc == 0) {
        atomicAdd(&sh1[m0+lr  ], sum0); atomicAdd(&sq1[m0+lr  ], ssq0);
        atomicAdd(&sh1[m0+8+lr], sum1); atomicAdd(&sq1[m0+8+lr], ssq1);
    }
    __syncthreads();
    if (t < CH) { atomicAdd(&g_s1[t], (double)sh1[t]); atomicAdd(&g_ss1[t], (double)sq1[t]); }
}

// ---------------- K3b: finalize block-1 BN affine ----------------
__global__ void k3b_fold1(const float* __restrict__ gamma, const float* __restrict__ beta) {
    int o = threadIdx.x;
    if (o >= CH) return;
    double inv = 1.0 / ((double)BATCH * NPTS * KNN);
    double mu  = g_s1[o] * inv;
    double var = g_ss1[o] * inv - mu*mu;
    double a = (double)gamma[o] / sqrt(var + 1e-5);
    g_a1[o] = (float)a;
    g_c1[o] = (float)((double)beta[o] - a*mu);
}

// ---------------- K4: g2 = relu(BN1(h1)); h2 = w2 g2 + b2; max over k -> out ----------------
__global__ __launch_bounds__(256, 2) void k4_out(const float* __restrict__ w2, const float* __restrict__ b2,
                                                  float* __restrict__ out) {
    extern __shared__ float sm4[];
    float* g2s = sm4;                  // [256][GPAD]
    float* w2s = sm4 + SAMP*GPAD;      // [64][64]
    __shared__ __align__(16) float a1s[CH];
    __shared__ __align__(16) float c1s[CH];
    __shared__ float b2s[CH];
    const int t  = threadIdx.x;
    const int b  = blockIdx.x >> 8;
    const int n0blk = (blockIdx.x & 255) * NTILE;

    for (int idx = t; idx < CH*CH; idx += 256) w2s[idx] = w2[idx];
    if (t < CH) { a1s[t]=g_a1[t]; c1s[t]=g_c1[t]; b2s[t]=b2[t]; }
    __syncthreads();

    // BN + relu + write to padded [s][c] tile (h1 stored [s][o] -> coalesced)
    const float* hb = g_h1 + (size_t)blockIdx.x * (SAMP*CH);
    for (int idx = t*4; idx < SAMP*CH; idx += 256*4) {
        float4 v = *(const float4*)(hb + idx);
        int o = idx & 63, s = idx >> 6;
        float4 a = *(const float4*)(a1s + o);
        float4 c = *(const float4*)(c1s + o);
        v.x = fmaxf(fmaf(a.x, v.x, c.x), 0.f);
        v.y = fmaxf(fmaf(a.y, v.y, c.y), 0.f);
        v.z = fmaxf(fmaf(a.z, v.z, c.z), 0.f);
        v.w = fmaxf(fmaf(a.w, v.w, c.w), 0.f);
        *(float4*)(g2s + s*GPAD + o) = v;
    }
    __syncthreads();

    const int warp = t >> 5, lane = t & 31, lr = lane >> 2, lc = lane & 3;
    const int m0 = (warp & 3) * 16, shalf = warp >> 2;

    uint32_t ahi[8][4], alo[8][4];
    #pragma unroll
    for (int kk = 0; kk < 8; ++kk) {
        int c0i = kk*8 + lc;
        tf32_split(w2s[(m0+lr  )*CH + c0i    ], ahi[kk][0], alo[kk][0]);
        tf32_split(w2s[(m0+lr+8)*CH + c0i    ], ahi[kk][1], alo[kk][1]);
        tf32_split(w2s[(m0+lr  )*CH + c0i + 4], ahi[kk][2], alo[kk][2]);
        tf32_split(w2s[(m0+lr+8)*CH + c0i + 4], ahi[kk][3], alo[kk][3]);
    }

    float bias0 = b2s[m0+lr], bias1 = b2s[m0+8+lr];
    float prev0 = 0.f, prev1 = 0.f;

    for (int nt = 0; nt < 16; ++nt) {
        const int n0 = shalf*128 + nt*8;
        float h0=bias0,h1=bias0,h2=bias1,h3=bias1;
        float m0a=0,m1a=0,m2a=0,m3a=0;
        float l0=0,l1=0,l2=0,l3=0;
        const float* grow = g2s + (n0+lr)*GPAD;
        #pragma unroll
        for (int kk = 0; kk < 8; ++kk) {
            float b0f = grow[kk*8 + lc];
            float b1f = grow[kk*8 + lc + 4];
            uint32_t bh0, bl0, bh1, bl1;
            tf32_split(b0f, bh0, bl0);
            tf32_split(b1f, bh1, bl1);
            mma_tf32(h0,h1,h2,h3, ahi[kk][0],ahi[kk][1],ahi[kk][2],ahi[kk][3], bh0,bh1);
            mma_tf32(m0a,m1a,m2a,m3a, ahi[kk][0],ahi[kk][1],ahi[kk][2],ahi[kk][3], bl0,bl1);
            mma_tf32(l0,l1,l2,l3, alo[kk][0],alo[kk][1],alo[kk][2],alo[kk][3], bh0,bh1);
        }
        float c0 = h0 + (m0a + l0);
        float c1 = h1 + (m1a + l1);
        float c2 = h2 + (m2a + l2);
        float c3 = h3 + (m3a + l3);
        // max over this n-tile's samples: lane holds s=n0+2lc, +1
        float p0 = fmaxf(c0, c1);                 // channel m0+lr
        float p1 = fmaxf(c2, c3);                 // channel m0+8+lr
        p0 = fmaxf(p0, __shfl_xor_sync(0xFFFFFFFFu, p0, 1));
        p0 = fmaxf(p0, __shfl_xor_sync(0xFFFFFFFFu, p0, 2));
        p1 = fmaxf(p1, __shfl_xor_sync(0xFFFFFFFFu, p1, 1));
        p1 = fmaxf(p1, __shfl_xor_sync(0xFFFFFFFFu, p1, 2));
        if (nt & 1) {
            // combine k-halves -> full point; point = shalf*8 + nt/2
            if (lc == 0) {
                int n = n0blk + shalf*8 + (nt >> 1);
                out[((size_t)(b*CH + m0+lr  ))*NPTS + n] = fmaxf(prev0, p0);
                out[((size_t)(b*CH + m0+8+lr))*NPTS + n] = fmaxf(prev1, p1);
            }
        } else {
            prev0 = p0; prev1 = p1;
        }
    }
}

// ---------------- launch ----------------
extern "C" void kernel_launch(void* const* d_in, const int* in_sizes, int n_in,
                              void* d_out, int out_size) {
    const float* xyz   = (const float*)d_in[0];
    const float* w1    = (const float*)d_in[1];
    const float* b1    = (const float*)d_in[2];
    const float* w2    = (const float*)d_in[3];
    const float* b2    = (const float*)d_in[4];
    const float* gamma = (const float*)d_in[5];
    const float* beta  = (const float*)d_in[6];
    float* out = (float*)d_out;
    (void)in_sizes; (void)n_in; (void)out_size;

    const int smemMM = (SAMP*GPAD + CH*CH) * 4;   // 86016 B

    cudaFuncSetAttribute(k1_knn, cudaFuncAttributeMaxDynamicSharedMemorySize, 65536);
    cudaFuncSetAttribute(k3_h1,  cudaFuncAttributeMaxDynamicSharedMemorySize, smemMM);
    cudaFuncSetAttribute(k4_out, cudaFuncAttributeMaxDynamicSharedMemorySize, smemMM);

    k0_init<<<1, 256>>>();
    k1_knn<<<128, 256, 65536>>>(xyz);
    k2_fold0<<<1, 64>>>(w1, b1, gamma, beta);
    k3_h1<<<NBLK, 256, smemMM>>>(w2, b2);
    k3b_fold1<<<1, 64>>>(gamma, beta);
    k4_out<<<NBLK, 256, smemMM>>>(w2, b2, out);
}